// round 12
// baseline (speedup 1.0000x reference)
#include <cuda_runtime.h>

#define TT 512
#define BB 256
#define DD 256
#define HH 256
#define DH 512
#define TB (TT*BB)

// scratch (allocation-free rule: static __device__ arrays)
// g_trig4[(t*6 + p)*256 + h] = {cos j=2p, sin 2p, cos 2p+1, sin 2p+1} for row (t,h)
__device__ float4 g_trig4[TT * 6 * 256];
__device__ __align__(16) float g_hseq[TT * HH];   // hvec per step
__device__ __align__(16) float g_cvec[HH];        // final cell state

// named producer/consumer barriers (384 = full CTA count each phase)
#define BAR_ARV(id)  asm volatile("bar.arrive %0, %1;" :: "r"(id), "r"(384) : "memory")
#define BAR_WAIT(id) asm volatile("bar.sync %0, %1;"   :: "r"(id), "r"(384) : "memory")

// accurate tanh (2 MUFU) for the cell-state nonlinearity (arg up to ~±2.1)
__device__ __forceinline__ float ftanh(float x) {
    return __fmaf_rn(2.0f, __fdividef(1.0f, 1.0f + __expf(-2.0f * x)), -1.0f);
}
// Taylor tanh on |u|<=0.55, err < 1.2e-5 (FMA pipe only)
__device__ __forceinline__ float tanh_small(float u) {
    float u2 = u * u;
    float p = __fmaf_rn(u2, 0.021869489f, -0.053968254f);
    p = __fmaf_rn(u2, p, 0.133333333f);
    p = __fmaf_rn(u2, p, -0.333333333f);
    return __fmaf_rn(u * u2, p, u);
}
// sigmoid for |x|<=1 : 0.5 + 0.5*tanh(x/2), zero MUFU
__device__ __forceinline__ float fsig_poly(float x) {
    return __fmaf_rn(0.5f, tanh_small(0.5f * x), 0.5f);
}
// tanh for |z|<=1 : 2t/(1+t^2), t=tanh(z/2), one MUFU (rcp)
__device__ __forceinline__ float ftanh_poly(float z) {
    float t = tanh_small(0.5f * z);
    return __fdividef(2.0f * t, __fmaf_rn(t, t, 1.0f));
}

// ---------------------------------------------------------------------------
// Kernel A: xp[t,h,j] = sum_d W_g[q,d]*x[t,h,d] + b_g[q] + phi_g[q]
// Warp-per-row; 12 used W rows in REGISTERS; tree-combined multi-reduce
// (24 useful SHFLs for 12 sums); x prefetched at distance 3; paired STG.128.
// ---------------------------------------------------------------------------
__global__ __launch_bounds__(128, 3) void precompute_kernel(
    const float* __restrict__ x,
    const float* __restrict__ Wf, const float* __restrict__ bf, const float* __restrict__ pf,
    const float* __restrict__ Wi, const float* __restrict__ bi, const float* __restrict__ pi,
    const float* __restrict__ Wu, const float* __restrict__ bu, const float* __restrict__ pu,
    const float* __restrict__ Wo, const float* __restrict__ bo, const float* __restrict__ po)
{
    int tid = threadIdx.x;
    int lane = tid & 31;
    int gwarp = (blockIdx.x * 128 + tid) >> 5;
    int nwarp = (gridDim.x * 128) >> 5;
    const unsigned FULL = 0xffffffffu;

    float4 wa[12], wb[12];
#pragma unroll
    for (int j = 0; j < 12; ++j) {
        const float* Ws = (j < 3) ? Wf : (j < 6) ? Wi : (j < 9) ? Wu : Wo;
        int q = 1 + (j % 3);
        const float4* r4 = (const float4*)(Ws + q * DH);
        wa[j] = r4[lane];
        wb[j] = r4[32 + lane];
    }

    int b4 = (lane >> 4) & 1, b3 = (lane >> 3) & 1, b2 = (lane >> 2) & 1;
    int myj = (lane & 2) ? (8 + b4 + 2 * b3) : (b4 + 2 * b3 + 4 * b2);
    float off;
    {
        const float* bs = (myj < 3) ? bf : (myj < 6) ? bi : (myj < 9) ? bu : bo;
        const float* ps = (myj < 3) ? pf : (myj < 6) ? pi : (myj < 9) ? pu : po;
        int q = 1 + (myj % 3);
        off = bs[q] + ps[q];
    }
    bool writer = ((lane & 0x13) == 0) || ((lane & 0x17) == 2);
    int plane = myj >> 1;

    const float4* x4 = (const float4*)x;

    int row = gwarp;
    if (row >= TB) return;
    // software pipeline, prefetch distance 3
    float4 x0a = x4[row * 64 + lane];
    float4 x0b = x4[row * 64 + 32 + lane];
    float4 x1a = make_float4(0.f,0.f,0.f,0.f), x1b = x1a, x2a = x1a, x2b = x1a;
    if (row + nwarp < TB) {
        x1a = x4[(row + nwarp) * 64 + lane];
        x1b = x4[(row + nwarp) * 64 + 32 + lane];
    }
    if (row + 2 * nwarp < TB) {
        x2a = x4[(row + 2 * nwarp) * 64 + lane];
        x2b = x4[(row + 2 * nwarp) * 64 + 32 + lane];
    }

#pragma unroll 3
    for (; row < TB; row += nwarp) {
        int frow = row + 3 * nwarp;
        float4 fa, fb;
        if (frow < TB) {
            fa = x4[frow * 64 + lane];
            fb = x4[frow * 64 + 32 + lane];
        }

        float v[12];
#pragma unroll
        for (int j = 0; j < 12; ++j) {
            v[j] = x0a.x * wa[j].x + x0a.y * wa[j].y + x0a.z * wa[j].z + x0a.w * wa[j].w
                 + x0b.x * wb[j].x + x0b.y * wb[j].y + x0b.z * wb[j].z + x0b.w * wb[j].w;
        }

        // tree-combined multi-reduce: 12 sums in 24 shfls
#pragma unroll
        for (int j = 0; j < 12; ++j)
            v[j] += __shfl_xor_sync(FULL, v[j], 16);
        float w[6];
#pragma unroll
        for (int k = 0; k < 6; ++k) {
            w[k] = (lane & 16) ? v[2 * k + 1] : v[2 * k];
            w[k] += __shfl_xor_sync(FULL, w[k], 8);
        }
        float y[3];
#pragma unroll
        for (int m = 0; m < 3; ++m) {
            y[m] = (lane & 8) ? w[2 * m + 1] : w[2 * m];
            y[m] += __shfl_xor_sync(FULL, y[m], 4);
        }
        float z0 = (lane & 4) ? y[1] : y[0];
        float z1 = y[2];
        z0 += __shfl_xor_sync(FULL, z0, 2);
        z1 += __shfl_xor_sync(FULL, z1, 2);
        float u = (lane & 2) ? z1 : z0;
        u += __shfl_xor_sync(FULL, u, 1);

        float th = u + off;
        float s, c;
        __sincosf(th, &s, &c);
        float c1 = __shfl_xor_sync(FULL, c, 16);
        float s1 = __shfl_xor_sync(FULL, s, 16);
        if (writer) {
            int t = row >> 8, h = row & 255;
            g_trig4[(t * 6 + plane) * 256 + h] = make_float4(c, s, c1, s1);
        }

        x0a = x1a; x0b = x1b;
        x1a = x2a; x1b = x2b;
        x2a = fa;  x2b = fb;
    }
}

// ---------------------------------------------------------------------------
// Kernel B: warp-specialized recurrence. 1 block, 384 threads.
//   gate warps 0-7  (256 thr): per-h gate math (h = tid), cv in register
//   reduce warps 8-11 (128 thr): warp rw owns gate matrix rw; 3 hdot
//     tree-dots + interleaved butterflies; lanes 0-5 do cos/sin in parallel.
// barrier 1: hv ready (gates arrive, reducers wait)
// barrier 2: cs ready (reducers arrive, gates wait)
// ---------------------------------------------------------------------------
__device__ __forceinline__ void gate_half(
    int t, int pf_t, int tid,
    float4& v0, float4& v1, float4& v2, float4& v3, float4& v4, float4& v5,
    float& cvr, float* hv_sm, float* chs, float* shs)
{
    const float4* C = (const float4*)chs;
    const float4* S = (const float4*)shs;
    float4 c0 = C[0], c1 = C[1], c2 = C[2];
    float4 s0 = S[0], s1 = S[1], s2 = S[2];

    float r0  = v0.x * c0.x - v0.y * s0.x;
    float r1  = v0.z * c0.y - v0.w * s0.y;
    float r2  = v1.x * c0.z - v1.y * s0.z;
    float r3  = v1.z * c0.w - v1.w * s0.w;
    float r4  = v2.x * c1.x - v2.y * s1.x;
    float r5  = v2.z * c1.y - v2.w * s1.y;
    float r6  = v3.x * c1.z - v3.y * s1.z;
    float r7  = v3.z * c1.w - v3.w * s1.w;
    float r8  = v4.x * c2.x - v4.y * s2.x;
    float r9  = v4.z * c2.y - v4.w * s2.y;
    float r10 = v5.x * c2.z - v5.y * s2.z;
    float r11 = v5.z * c2.w - v5.w * s2.w;

    float f  = fsig_poly(r0 * r1 * r2);
    float ig = fsig_poly(r3 * r4 * r5) * ftanh_poly(r6 * r7 * r8);
    float o  = fsig_poly(r9 * r10 * r11);

    cvr = __fmaf_rn(f, cvr, ig);
    float hx = o * ftanh(cvr);
    hv_sm[tid] = hx;
    BAR_ARV(1);                     // hv ready

    g_hseq[t * 256 + tid] = hx;     // off-chain
    if (pf_t < TT) {                // prefetch distance 2, coalesced
        const float4* tp = g_trig4 + pf_t * 6 * 256 + tid;
        v0 = tp[0];    v1 = tp[256];  v2 = tp[512];
        v3 = tp[768];  v4 = tp[1024]; v5 = tp[1280];
    }
    BAR_WAIT(2);                    // cs(t) ready for next half-step
}

// pairwise-tree 8-element dot: chain mul+fma (8) + 2 add levels (8) ~ 16 cyc
__device__ __forceinline__ float dot8(float4 wa, float4 wb, float4 ha, float4 hb)
{
    float m0 = __fmaf_rn(wa.y, ha.y, wa.x * ha.x);
    float m1 = __fmaf_rn(wa.w, ha.w, wa.z * ha.z);
    float m2 = __fmaf_rn(wb.y, hb.y, wb.x * hb.x);
    float m3 = __fmaf_rn(wb.w, hb.w, wb.z * hb.z);
    return (m0 + m1) + (m2 + m3);
}

__global__ __launch_bounds__(384, 1) void recurrence_kernel(
    const float* __restrict__ Wf, const float* __restrict__ Wi,
    const float* __restrict__ Wu, const float* __restrict__ Wo)
{
    __shared__ __align__(16) float hv_sm[256];
    __shared__ __align__(16) float chs[12];
    __shared__ __align__(16) float shs[12];

    int tid = threadIdx.x;
    int lane = tid & 31, warp = tid >> 5;

    if (tid < 12) { chs[tid] = 1.0f; shs[tid] = 0.0f; }  // hvec0 = 0 -> hdot = 0
    __syncthreads();

    if (warp < 8) {
        // ---------------- gate role ----------------
        float cvr = 0.0f;
        float4 A0, A1, A2, A3, A4, A5;
        float4 B0, B1, B2, B3, B4, B5;
        {
            const float4* tp0 = g_trig4 + tid;
            A0 = tp0[0];    A1 = tp0[256];  A2 = tp0[512];
            A3 = tp0[768];  A4 = tp0[1024]; A5 = tp0[1280];
            const float4* tp1 = g_trig4 + 6 * 256 + tid;
            B0 = tp1[0];    B1 = tp1[256];  B2 = tp1[512];
            B3 = tp1[768];  B4 = tp1[1024]; B5 = tp1[1280];
        }
        for (int t = 0; t < TT; t += 2) {
            gate_half(t,     t + 2, tid, A0, A1, A2, A3, A4, A5,
                      cvr, hv_sm, chs, shs);
            gate_half(t + 1, t + 3, tid, B0, B1, B2, B3, B4, B5,
                      cvr, hv_sm, chs, shs);
        }
        g_cvec[tid] = cvr;
    } else {
        // ---------------- reduce role ----------------
        int rw = warp - 8;   // 0..3 -> Wf, Wi, Wu, Wo ; j = rw*3 + k, q = 1+k
        const float* Wsel = (rw == 0) ? Wf : (rw == 1) ? Wi : (rw == 2) ? Wu : Wo;
        float4 wa[3], wb[3];
#pragma unroll
        for (int k = 0; k < 3; ++k) {
            const float4* Wr4 = (const float4*)(Wsel + (1 + k) * DH + DD);
            wa[k] = Wr4[lane];
            wb[k] = Wr4[32 + lane];
        }
        const float4* hv4 = (const float4*)hv_sm;
        // per-lane sincos assignment: lanes 0..5 -> (k = lane>>1, odd = sin)
        int kk = lane >> 1;
        float* dst = (lane & 1) ? shs : chs;
        int jj = rw * 3 + kk;

        for (int t = 0; t < TT; ++t) {
            BAR_WAIT(1);            // hv ready
            float4 ha = hv4[lane];
            float4 hb = hv4[32 + lane];
            float s0 = dot8(wa[0], wb[0], ha, hb);
            float s1 = dot8(wa[1], wb[1], ha, hb);
            float s2 = dot8(wa[2], wb[2], ha, hb);
            // 3 interleaved butterflies (independent latency chains)
#pragma unroll
            for (int off = 16; off > 0; off >>= 1) {
                s0 += __shfl_xor_sync(0xffffffffu, s0, off);
                s1 += __shfl_xor_sync(0xffffffffu, s1, off);
                s2 += __shfl_xor_sync(0xffffffffu, s2, off);
            }
            if (lane < 6) {
                float sv = (kk == 0) ? s0 : (kk == 1) ? s1 : s2;
                float r = (lane & 1) ? __sinf(sv) : __cosf(sv);
                dst[jj] = r;
            }
            BAR_ARV(2);             // cs ready
        }
    }
}

// ---------------------------------------------------------------------------
// Kernel C: broadcast outputs. out = [outs (T,B,H) | hx (B,H) | cx (B,H)],
// every b-row identical. Pure write bandwidth, float4.
// ---------------------------------------------------------------------------
__global__ void writeout_kernel(float4* __restrict__ out4)
{
    const int OUTS4 = TT * BB * (HH / 4);   // 8388608
    const int BH4 = BB * (HH / 4);          // 16384
    int i4 = blockIdx.x * blockDim.x + threadIdx.x;
    const float4* hs4 = (const float4*)g_hseq;
    const float4* cv4 = (const float4*)g_cvec;
    if (i4 < OUTS4) {
        int t = i4 >> 14;          // / (B*H/4)
        int h4 = i4 & 63;
        out4[i4] = hs4[t * 64 + h4];
    } else if (i4 < OUTS4 + BH4) {
        int h4 = i4 & 63;
        out4[i4] = hs4[(TT - 1) * 64 + h4];
    } else if (i4 < OUTS4 + 2 * BH4) {
        int h4 = i4 & 63;
        out4[i4] = cv4[h4];
    }
}

// no-ops: place the recurrence kernel at absolute launch index 3, which is
// the slot ncu's fixed -s 5 -c 1 capture lands on (calibrated R5-R11:
// 3-kernel stream profiled idx-3=precompute; 4-kernel stream profiled
// idx-3=noop). Order: pre(0), noop(1), noop(2), RECURRENCE(3), writeout(4).
__global__ void noop_kernel() {}

extern "C" void kernel_launch(void* const* d_in, const int* in_sizes, int n_in,
                              void* d_out, int out_size)
{
    const float* x  = (const float*)d_in[0];
    const float* Wf = (const float*)d_in[1];
    const float* bf = (const float*)d_in[2];
    const float* pf = (const float*)d_in[3];
    const float* Wi = (const float*)d_in[4];
    const float* bi = (const float*)d_in[5];
    const float* pi = (const float*)d_in[6];
    const float* Wu = (const float*)d_in[7];
    const float* bu = (const float*)d_in[8];
    const float* pu = (const float*)d_in[9];
    const float* Wo = (const float*)d_in[10];
    const float* bo = (const float*)d_in[11];
    const float* po = (const float*)d_in[12];

    precompute_kernel<<<444, 128>>>(x, Wf, bf, pf, Wi, bi, pi,
                                       Wu, bu, pu, Wo, bo, po);
    noop_kernel<<<1, 32>>>();
    noop_kernel<<<1, 32>>>();
    recurrence_kernel<<<1, 384>>>(Wf, Wi, Wu, Wo);

    const int total4 = (TT * BB * HH + 2 * BB * HH) / 4;   // 8421376
    writeout_kernel<<<(total4 + 255) / 256, 256>>>((float4*)d_out);
}

// round 13
// speedup vs baseline: 1.1268x; 1.1268x over previous
#include <cuda_runtime.h>

#define TT 512
#define BB 256
#define DD 256
#define HH 256
#define DH 512
#define TB (TT*BB)

// scratch (allocation-free rule: static __device__ arrays)
// g_trig4[(t*6 + p)*256 + h] = {cos j=2p, sin 2p, cos 2p+1, sin 2p+1} for row (t,h)
__device__ float4 g_trig4[TT * 6 * 256];
__device__ __align__(16) float g_hseq[TT * HH];   // hvec per step
__device__ __align__(16) float g_cvec[HH];        // final cell state

// named producer/consumer barriers (384 = full CTA count each phase)
#define BAR_ARV(id)  asm volatile("bar.arrive %0, %1;" :: "r"(id), "r"(384) : "memory")
#define BAR_WAIT(id) asm volatile("bar.sync %0, %1;"   :: "r"(id), "r"(384) : "memory")

// HW tanh (MUFU.TANH, sm_75+): 1 instruction, rel err ~2^-11.
__device__ __forceinline__ float tanh_hw(float x) {
    float r;
    asm("tanh.approx.f32 %0, %1;" : "=f"(r) : "f"(x));
    return r;
}
// sigmoid(x) = 0.5 + 0.5*tanh(x/2): 2 FMA-pipe ops + 1 MUFU
__device__ __forceinline__ float fsig_hw(float x) {
    return __fmaf_rn(0.5f, tanh_hw(0.5f * x), 0.5f);
}

// ---------------------------------------------------------------------------
// Kernel A: xp[t,h,j] = sum_d W_g[q,d]*x[t,h,d] + b_g[q] + phi_g[q]
// Warp-per-row; 12 used W rows in REGISTERS; tree-combined multi-reduce
// (24 useful SHFLs for 12 sums); x prefetched at distance 3; paired STG.128.
// ---------------------------------------------------------------------------
__global__ __launch_bounds__(128, 3) void precompute_kernel(
    const float* __restrict__ x,
    const float* __restrict__ Wf, const float* __restrict__ bf, const float* __restrict__ pf,
    const float* __restrict__ Wi, const float* __restrict__ bi, const float* __restrict__ pi,
    const float* __restrict__ Wu, const float* __restrict__ bu, const float* __restrict__ pu,
    const float* __restrict__ Wo, const float* __restrict__ bo, const float* __restrict__ po)
{
    int tid = threadIdx.x;
    int lane = tid & 31;
    int gwarp = (blockIdx.x * 128 + tid) >> 5;
    int nwarp = (gridDim.x * 128) >> 5;
    const unsigned FULL = 0xffffffffu;

    float4 wa[12], wb[12];
#pragma unroll
    for (int j = 0; j < 12; ++j) {
        const float* Ws = (j < 3) ? Wf : (j < 6) ? Wi : (j < 9) ? Wu : Wo;
        int q = 1 + (j % 3);
        const float4* r4 = (const float4*)(Ws + q * DH);
        wa[j] = r4[lane];
        wb[j] = r4[32 + lane];
    }

    int b4 = (lane >> 4) & 1, b3 = (lane >> 3) & 1, b2 = (lane >> 2) & 1;
    int myj = (lane & 2) ? (8 + b4 + 2 * b3) : (b4 + 2 * b3 + 4 * b2);
    float off;
    {
        const float* bs = (myj < 3) ? bf : (myj < 6) ? bi : (myj < 9) ? bu : bo;
        const float* ps = (myj < 3) ? pf : (myj < 6) ? pi : (myj < 9) ? pu : po;
        int q = 1 + (myj % 3);
        off = bs[q] + ps[q];
    }
    bool writer = ((lane & 0x13) == 0) || ((lane & 0x17) == 2);
    int plane = myj >> 1;

    const float4* x4 = (const float4*)x;

    int row = gwarp;
    if (row >= TB) return;
    // software pipeline, prefetch distance 3
    float4 x0a = x4[row * 64 + lane];
    float4 x0b = x4[row * 64 + 32 + lane];
    float4 x1a = make_float4(0.f,0.f,0.f,0.f), x1b = x1a, x2a = x1a, x2b = x1a;
    if (row + nwarp < TB) {
        x1a = x4[(row + nwarp) * 64 + lane];
        x1b = x4[(row + nwarp) * 64 + 32 + lane];
    }
    if (row + 2 * nwarp < TB) {
        x2a = x4[(row + 2 * nwarp) * 64 + lane];
        x2b = x4[(row + 2 * nwarp) * 64 + 32 + lane];
    }

#pragma unroll 3
    for (; row < TB; row += nwarp) {
        int frow = row + 3 * nwarp;
        float4 fa, fb;
        if (frow < TB) {
            fa = x4[frow * 64 + lane];
            fb = x4[frow * 64 + 32 + lane];
        }

        float v[12];
#pragma unroll
        for (int j = 0; j < 12; ++j) {
            v[j] = x0a.x * wa[j].x + x0a.y * wa[j].y + x0a.z * wa[j].z + x0a.w * wa[j].w
                 + x0b.x * wb[j].x + x0b.y * wb[j].y + x0b.z * wb[j].z + x0b.w * wb[j].w;
        }

        // tree-combined multi-reduce: 12 sums in 24 shfls
#pragma unroll
        for (int j = 0; j < 12; ++j)
            v[j] += __shfl_xor_sync(FULL, v[j], 16);
        float w[6];
#pragma unroll
        for (int k = 0; k < 6; ++k) {
            w[k] = (lane & 16) ? v[2 * k + 1] : v[2 * k];
            w[k] += __shfl_xor_sync(FULL, w[k], 8);
        }
        float y[3];
#pragma unroll
        for (int m = 0; m < 3; ++m) {
            y[m] = (lane & 8) ? w[2 * m + 1] : w[2 * m];
            y[m] += __shfl_xor_sync(FULL, y[m], 4);
        }
        float z0 = (lane & 4) ? y[1] : y[0];
        float z1 = y[2];
        z0 += __shfl_xor_sync(FULL, z0, 2);
        z1 += __shfl_xor_sync(FULL, z1, 2);
        float u = (lane & 2) ? z1 : z0;
        u += __shfl_xor_sync(FULL, u, 1);

        float th = u + off;
        float s, c;
        __sincosf(th, &s, &c);
        float c1 = __shfl_xor_sync(FULL, c, 16);
        float s1 = __shfl_xor_sync(FULL, s, 16);
        if (writer) {
            int t = row >> 8, h = row & 255;
            g_trig4[(t * 6 + plane) * 256 + h] = make_float4(c, s, c1, s1);
        }

        x0a = x1a; x0b = x1b;
        x1a = x2a; x1b = x2b;
        x2a = fa;  x2b = fb;
    }
}

// ---------------------------------------------------------------------------
// Kernel B: warp-specialized recurrence. 1 block, 384 threads.
// ISSUE-BOUND (ncu R12: issue 23.8%, mem ~0) -> minimize gate instructions:
// all nonlinearities through 1-op MUFU.TANH.
//   gate warps 0-7  (256 thr): per-h gate math (h = tid), cv in register
//   reduce warps 8-11 (128 thr): warp rw owns gate matrix rw; 3 hdot
//     tree-dots + interleaved butterflies; lanes 0-5 do cos/sin in parallel.
// barrier 1: hv ready (gates arrive, reducers wait)
// barrier 2: cs ready (reducers arrive, gates wait)
// ---------------------------------------------------------------------------
__device__ __forceinline__ void gate_half(
    int t, int pf_t, int tid,
    float4& v0, float4& v1, float4& v2, float4& v3, float4& v4, float4& v5,
    float& cvr, float* hv_sm, float* chs, float* shs)
{
    const float4* C = (const float4*)chs;
    const float4* S = (const float4*)shs;
    float4 c0 = C[0], c1 = C[1], c2 = C[2];
    float4 s0 = S[0], s1 = S[1], s2 = S[2];

    float r0  = v0.x * c0.x - v0.y * s0.x;
    float r1  = v0.z * c0.y - v0.w * s0.y;
    float r2  = v1.x * c0.z - v1.y * s0.z;
    float r3  = v1.z * c0.w - v1.w * s0.w;
    float r4  = v2.x * c1.x - v2.y * s1.x;
    float r5  = v2.z * c1.y - v2.w * s1.y;
    float r6  = v3.x * c1.z - v3.y * s1.z;
    float r7  = v3.z * c1.w - v3.w * s1.w;
    float r8  = v4.x * c2.x - v4.y * s2.x;
    float r9  = v4.z * c2.y - v4.w * s2.y;
    float r10 = v5.x * c2.z - v5.y * s2.z;
    float r11 = v5.z * c2.w - v5.w * s2.w;

    float f  = fsig_hw(r0 * r1 * r2);
    float ig = fsig_hw(r3 * r4 * r5) * tanh_hw(r6 * r7 * r8);
    float o  = fsig_hw(r9 * r10 * r11);

    cvr = __fmaf_rn(f, cvr, ig);
    float hx = o * tanh_hw(cvr);
    hv_sm[tid] = hx;
    BAR_ARV(1);                     // hv ready

    g_hseq[t * 256 + tid] = hx;     // off-chain
    if (pf_t < TT) {                // prefetch distance 2, coalesced
        const float4* tp = g_trig4 + pf_t * 6 * 256 + tid;
        v0 = tp[0];    v1 = tp[256];  v2 = tp[512];
        v3 = tp[768];  v4 = tp[1024]; v5 = tp[1280];
    }
    BAR_WAIT(2);                    // cs(t) ready for next half-step
}

// pairwise-tree 8-element dot: chain mul+fma (8) + 2 add levels (8) ~ 16 cyc
__device__ __forceinline__ float dot8(float4 wa, float4 wb, float4 ha, float4 hb)
{
    float m0 = __fmaf_rn(wa.y, ha.y, wa.x * ha.x);
    float m1 = __fmaf_rn(wa.w, ha.w, wa.z * ha.z);
    float m2 = __fmaf_rn(wb.y, hb.y, wb.x * hb.x);
    float m3 = __fmaf_rn(wb.w, hb.w, wb.z * hb.z);
    return (m0 + m1) + (m2 + m3);
}

__global__ __launch_bounds__(384, 1) void recurrence_kernel(
    const float* __restrict__ Wf, const float* __restrict__ Wi,
    const float* __restrict__ Wu, const float* __restrict__ Wo)
{
    __shared__ __align__(16) float hv_sm[256];
    __shared__ __align__(16) float chs[12];
    __shared__ __align__(16) float shs[12];

    int tid = threadIdx.x;
    int lane = tid & 31, warp = tid >> 5;

    if (tid < 12) { chs[tid] = 1.0f; shs[tid] = 0.0f; }  // hvec0 = 0 -> hdot = 0
    __syncthreads();

    if (warp < 8) {
        // ---------------- gate role ----------------
        float cvr = 0.0f;
        float4 A0, A1, A2, A3, A4, A5;
        float4 B0, B1, B2, B3, B4, B5;
        {
            const float4* tp0 = g_trig4 + tid;
            A0 = tp0[0];    A1 = tp0[256];  A2 = tp0[512];
            A3 = tp0[768];  A4 = tp0[1024]; A5 = tp0[1280];
            const float4* tp1 = g_trig4 + 6 * 256 + tid;
            B0 = tp1[0];    B1 = tp1[256];  B2 = tp1[512];
            B3 = tp1[768];  B4 = tp1[1024]; B5 = tp1[1280];
        }
        for (int t = 0; t < TT; t += 2) {
            gate_half(t,     t + 2, tid, A0, A1, A2, A3, A4, A5,
                      cvr, hv_sm, chs, shs);
            gate_half(t + 1, t + 3, tid, B0, B1, B2, B3, B4, B5,
                      cvr, hv_sm, chs, shs);
        }
        g_cvec[tid] = cvr;
    } else {
        // ---------------- reduce role ----------------
        int rw = warp - 8;   // 0..3 -> Wf, Wi, Wu, Wo ; j = rw*3 + k, q = 1+k
        const float* Wsel = (rw == 0) ? Wf : (rw == 1) ? Wi : (rw == 2) ? Wu : Wo;
        float4 wa[3], wb[3];
#pragma unroll
        for (int k = 0; k < 3; ++k) {
            const float4* Wr4 = (const float4*)(Wsel + (1 + k) * DH + DD);
            wa[k] = Wr4[lane];
            wb[k] = Wr4[32 + lane];
        }
        const float4* hv4 = (const float4*)hv_sm;
        // per-lane sincos assignment: lanes 0..5 -> (k = lane>>1, odd = sin)
        int kk = lane >> 1;
        float* dst = (lane & 1) ? shs : chs;
        int jj = rw * 3 + kk;

        for (int t = 0; t < TT; ++t) {
            BAR_WAIT(1);            // hv ready
            float4 ha = hv4[lane];
            float4 hb = hv4[32 + lane];
            float s0 = dot8(wa[0], wb[0], ha, hb);
            float s1 = dot8(wa[1], wb[1], ha, hb);
            float s2 = dot8(wa[2], wb[2], ha, hb);
            // 3 interleaved butterflies (independent latency chains)
#pragma unroll
            for (int off = 16; off > 0; off >>= 1) {
                s0 += __shfl_xor_sync(0xffffffffu, s0, off);
                s1 += __shfl_xor_sync(0xffffffffu, s1, off);
                s2 += __shfl_xor_sync(0xffffffffu, s2, off);
            }
            if (lane < 6) {
                float sv = (kk == 0) ? s0 : (kk == 1) ? s1 : s2;
                float r = (lane & 1) ? __sinf(sv) : __cosf(sv);
                dst[jj] = r;
            }
            BAR_ARV(2);             // cs ready
        }
    }
}

// ---------------------------------------------------------------------------
// Kernel C: broadcast outputs. out = [outs (T,B,H) | hx (B,H) | cx (B,H)],
// every b-row identical. Pure write bandwidth, float4.
// ---------------------------------------------------------------------------
__global__ void writeout_kernel(float4* __restrict__ out4)
{
    const int OUTS4 = TT * BB * (HH / 4);   // 8388608
    const int BH4 = BB * (HH / 4);          // 16384
    int i4 = blockIdx.x * blockDim.x + threadIdx.x;
    const float4* hs4 = (const float4*)g_hseq;
    const float4* cv4 = (const float4*)g_cvec;
    if (i4 < OUTS4) {
        int t = i4 >> 14;          // / (B*H/4)
        int h4 = i4 & 63;
        out4[i4] = hs4[t * 64 + h4];
    } else if (i4 < OUTS4 + BH4) {
        int h4 = i4 & 63;
        out4[i4] = hs4[(TT - 1) * 64 + h4];
    } else if (i4 < OUTS4 + 2 * BH4) {
        int h4 = i4 & 63;
        out4[i4] = cv4[h4];
    }
}

extern "C" void kernel_launch(void* const* d_in, const int* in_sizes, int n_in,
                              void* d_out, int out_size)
{
    const float* x  = (const float*)d_in[0];
    const float* Wf = (const float*)d_in[1];
    const float* bf = (const float*)d_in[2];
    const float* pf = (const float*)d_in[3];
    const float* Wi = (const float*)d_in[4];
    const float* bi = (const float*)d_in[5];
    const float* pi = (const float*)d_in[6];
    const float* Wu = (const float*)d_in[7];
    const float* bu = (const float*)d_in[8];
    const float* pu = (const float*)d_in[9];
    const float* Wo = (const float*)d_in[10];
    const float* bo = (const float*)d_in[11];
    const float* po = (const float*)d_in[12];

    precompute_kernel<<<444, 128>>>(x, Wf, bf, pf, Wi, bi, pi,
                                       Wu, bu, pu, Wo, bo, po);
    recurrence_kernel<<<1, 384>>>(Wf, Wi, Wu, Wo);

    const int total4 = (TT * BB * HH + 2 * BB * HH) / 4;   // 8421376
    writeout_kernel<<<(total4 + 255) / 256, 256>>>((float4*)d_out);
}